// round 16
// baseline (speedup 1.0000x reference)
#include <cuda_runtime.h>
#include <cuda_fp16.h>
#include <math.h>
#include <stdint.h>

// ---------------- problem constants ----------------
#define BB     8
#define HH     128
#define WW     384
#define CC     192
#define NHEAD  6
#define WSZ    8
#define SSZ    4
#define HDIM   32
#define NWIN   768
#define NTOK   64
#define HWSZ   (HH*WW)             // 49152
#define MTOK   (BB*HWSZ)           // 393216
#define C3     (3*CC)              // 576
#define MLPH   (4*CC)              // 768
#define SCALE  0.1767766952966369f
#define MCHUNK (MTOK/2)            // 196608 rows per MLP chunk (2 chunks)

// ---------------- scratch (aliased; keep <2GB total for host link) --------
__device__ float g_bufA[(size_t)MTOK * CC];    // win/att/mlp(half) reuse
__device__ float g_bufB[(size_t)MTOK * C3];    // qkv(h) -> (x1 | h2)
__device__ float g_biasT[NHEAD * NTOK * NTOK]; // rpb[rel_idx] pre-gathered
__device__ __half g_wh[C3*CC + CC*CC + MLPH*CC + CC*MLPH]; // fp16 weights

#define WOFF_QKV  0
#define WOFF_PROJ (C3*CC)
#define WOFF_FC1  (C3*CC + CC*CC)
#define WOFF_FC2  (C3*CC + CC*CC + MLPH*CC)
#define WTOT      (C3*CC + CC*CC + MLPH*CC + CC*MLPH)   // 442368

__device__ __forceinline__ int win_to_tok(int m) {
    int b  = m / HWSZ;
    int r  = m - b * HWSZ;
    int w  = r >> 6;
    int nt = r & 63;
    int wrow = w / 48;
    int wcol = w - wrow * 48;
    int sh = (wrow << 3) + (nt >> 3);
    int sw = (wcol << 3) + (nt & 7);
    int fh = (sh + SSZ) & (HH - 1);
    int fw = sw + SSZ; if (fw >= WW) fw -= WW;
    return b * HWSZ + fh * WW + fw;
}

// ---------------- merged prep: all weights -> fp16 -----------------------
__global__ void prep_kernel(const float* __restrict__ qkv_w,
                            const float* __restrict__ proj_w,
                            const float* __restrict__ fc1_w,
                            const float* __restrict__ fc2_w,
                            __half* __restrict__ wh) {
    int i = blockIdx.x * blockDim.x + threadIdx.x;
    if (i >= WTOT) return;
    float v;
    if (i < WOFF_PROJ)      v = qkv_w[i];
    else if (i < WOFF_FC1)  v = proj_w[i - WOFF_PROJ];
    else if (i < WOFF_FC2)  v = fc1_w[i - WOFF_FC1];
    else                    v = fc2_w[i - WOFF_FC2];
    wh[i] = __float2half_rn(v);
}
__global__ void bias_gather_kernel(const float* __restrict__ rpb,
                                   const int* __restrict__ rel_idx,
                                   float* __restrict__ biasT) {
    int i = blockIdx.x * blockDim.x + threadIdx.x;
    if (i >= NHEAD * NTOK * NTOK) return;
    int h = i / (NTOK * NTOK), e = i % (NTOK * NTOK);
    biasT[i] = rpb[rel_idx[e] * NHEAD + h];
}

// ---------------- LayerNorm (one warp per token) -> fp16 out --------------
template<bool GATHER>
__global__ void ln_kernel(const float* __restrict__ x,
                          const float* __restrict__ gamma,
                          const float* __restrict__ beta,
                          __half* __restrict__ out) {
    int warp = blockIdx.x * (blockDim.x >> 5) + (threadIdx.x >> 5);
    if (warp >= MTOK) return;
    int lane = threadIdx.x & 31;
    int src = GATHER ? win_to_tok(warp) : warp;
    const float* xr = x + (size_t)src * CC;
    float v[6], s = 0.f, ss = 0.f;
#pragma unroll
    for (int i = 0; i < 6; i++) {
        float t = xr[lane + i * 32];
        v[i] = t; s += t; ss += t * t;
    }
#pragma unroll
    for (int o = 16; o; o >>= 1) {
        s  += __shfl_xor_sync(0xffffffffu, s,  o);
        ss += __shfl_xor_sync(0xffffffffu, ss, o);
    }
    float mean = s * (1.f / CC);
    float var  = ss * (1.f / CC) - mean * mean;
    float rstd = rsqrtf(var + 1e-5f);
    __half* orow = out + (size_t)warp * CC;
#pragma unroll
    for (int i = 0; i < 6; i++) {
        int c = lane + i * 32;
        orow[c] = __float2half_rn((v[i] - mean) * rstd * gamma[c] + beta[c]);
    }
}

// ---------------- shared MMA helpers --------------------------------------
__device__ __forceinline__ void cp16(uint32_t s, const void* g) {
    asm volatile("cp.async.cg.shared.global [%0], [%1], 16;" :: "r"(s), "l"(g));
}
__device__ __forceinline__ void ldsm4(uint32_t* r, uint32_t addr) {
    asm volatile("ldmatrix.sync.aligned.m8n8.x4.shared.b16 {%0,%1,%2,%3}, [%4];"
        : "=r"(r[0]), "=r"(r[1]), "=r"(r[2]), "=r"(r[3]) : "r"(addr));
}
__device__ __forceinline__ void mma_f16(float c[4],
        uint32_t a0, uint32_t a1, uint32_t a2, uint32_t a3,
        uint32_t b0, uint32_t b1) {
    asm volatile(
        "mma.sync.aligned.m16n8k16.row.col.f32.f16.f16.f32 "
        "{%0,%1,%2,%3},{%4,%5,%6,%7},{%8,%9},{%0,%1,%2,%3};"
        : "+f"(c[0]), "+f"(c[1]), "+f"(c[2]), "+f"(c[3])
        : "r"(a0), "r"(a1), "r"(a2), "r"(a3), "r"(b0), "r"(b1));
}

#define EPI_QKVH 0   // out = half(acc + bias)
#define EPI_PROJ 1   // f32: scatter + residual
#define EPI_GELU 2   // half: gelu(acc + bias)
#define EPI_RES  3   // f32: residual

// common fused epilogue (warp tile 32x32, acc[2][4][4])
template<int EPI>
__device__ __forceinline__ void epilogue(float acc[2][4][4], int m0, int n0,
        int wm, int wn, int grp, int tig,
        const float* bias, const float* res, void* outv, int N) {
#pragma unroll
    for (int i = 0; i < 2; i++) {
#pragma unroll
        for (int h = 0; h < 2; h++) {
            int m = m0 + wm + i * 16 + grp + h * 8;
            int dst = (EPI == EPI_PROJ) ? win_to_tok(m) : m;
#pragma unroll
            for (int j = 0; j < 4; j++) {
                int n = n0 + wn + j * 8 + 2 * tig;
                float v0 = acc[i][j][h * 2 + 0] + bias[n];
                float v1 = acc[i][j][h * 2 + 1] + bias[n + 1];
                size_t oi = (size_t)dst * N + n;
                if (EPI == EPI_QKVH) {
                    *(__half2*)((__half*)outv + oi) = __floats2half2_rn(v0, v1);
                } else if (EPI == EPI_GELU) {
                    v0 = 0.5f * v0 * (1.f + erff(v0 * 0.70710678118654752f));
                    v1 = 0.5f * v1 * (1.f + erff(v1 * 0.70710678118654752f));
                    *(__half2*)((__half*)outv + oi) = __floats2half2_rn(v0, v1);
                } else {
                    float2 rv = *(const float2*)(res + oi);
                    float2 o = { v0 + rv.x, v1 + rv.y };
                    *(float2*)((float*)outv + oi) = o;
                }
            }
        }
    }
}

// ---------------- one-shot GEMM for K=192 ---------------------------------
// Whole K-panel in smem (stride 200 halves; conflict-free LDSM octets). ONE
// fill + ONE barrier, then a fully unrolled 12-step MMA loop with zero
// synchronization. A row = 192 halves = 24 x 16B chunks. BM=128 BN=64,
// 8 warps (4Mx2N), warp tile 32x32. 76.8KB dynamic smem -> 2 CTAs/SM.
#define OS_STRIDE 200
#define OS_SMEM   ((128 + 64) * OS_STRIDE * 2)

template<int EPI>
__global__ __launch_bounds__(256, 2)
void gemm_os(const __half* __restrict__ A, const __half* __restrict__ W,
             const float* __restrict__ bias, const float* __restrict__ res,
             void* __restrict__ outv, int M, int N) {
    extern __shared__ __half smem_h[];
    __half* As = smem_h;                       // 128 * OS_STRIDE
    __half* Bs = smem_h + 128 * OS_STRIDE;     // 64 * OS_STRIDE

    int tid  = threadIdx.x;
    int lane = tid & 31, warp = tid >> 5;
    int grp  = lane >> 2, tig = lane & 3;
    int sub  = lane >> 3, tr8 = lane & 7;
    int m0 = blockIdx.y * 128, n0 = blockIdx.x * 64;
    int wm = (warp & 3) * 32;
    int wn = (warp >> 2) * 32;

    uint32_t sA = (uint32_t)__cvta_generic_to_shared(As);
    uint32_t sB = (uint32_t)__cvta_generic_to_shared(Bs);

    // fill: rows have 24 x 16B chunks (192 halves). A: 128*24=3072 chunks,
    // 12 iters of 256 threads. B: 64*24=1536 chunks, 6 iters.
#pragma unroll
    for (int i = 0; i < 12; i++) {
        int c = tid + i * 256;
        int r = c / 24, col = (c % 24) * 8;
        cp16(sA + 2u * (r * OS_STRIDE + col),
             A + (size_t)(m0 + r) * CC + col);
    }
#pragma unroll
    for (int i = 0; i < 6; i++) {
        int c = tid + i * 256;
        int r = c / 24, col = (c % 24) * 8;
        cp16(sB + 2u * (r * OS_STRIDE + col),
             W + (size_t)(n0 + r) * CC + col);
    }
    asm volatile("cp.async.commit_group;");
    asm volatile("cp.async.wait_group 0;");
    __syncthreads();

    int rowAh[2], rowBh[2];
#pragma unroll
    for (int i = 0; i < 2; i++)
        rowAh[i] = (wm + i * 16 + (sub & 1) * 8 + tr8) * OS_STRIDE + (sub >> 1) * 8;
#pragma unroll
    for (int g = 0; g < 2; g++)
        rowBh[g] = (wn + g * 16 + (sub & 1) * 8 + tr8) * OS_STRIDE + (sub >> 1) * 8;

    float acc[2][4][4] = {};
#pragma unroll
    for (int ks = 0; ks < 12; ks++) {
        int kb = ks * 16;
        uint32_t a[2][4], b[2][4];
#pragma unroll
        for (int i = 0; i < 2; i++)
            ldsm4(a[i], sA + 2u * (rowAh[i] + kb));
        ldsm4(b[0], sB + 2u * (rowBh[0] + kb));
        ldsm4(b[1], sB + 2u * (rowBh[1] + kb));
#pragma unroll
        for (int i = 0; i < 2; i++)
#pragma unroll
            for (int j = 0; j < 4; j++) {
                int g = j >> 1, jn = j & 1;
                mma_f16(acc[i][j], a[i][0], a[i][1], a[i][2], a[i][3],
                        b[g][jn], b[g][2 + jn]);
            }
    }

    epilogue<EPI>(acc, m0, n0, wm, wn, grp, tig, bias, res, outv, N);
}

// ---------------- pipelined GEMM (used for fc2, K=768) --------------------
#define NSTAGE   4
#define AH_STAGE (128*40)
#define BH_STAGE (64*40)
#define SMEM_DYN (NSTAGE * (AH_STAGE + BH_STAGE) * 2)

template<int EPI>
__global__ __launch_bounds__(256, 3)
void gemm_tc(const __half* __restrict__ A, const __half* __restrict__ W,
             const float* __restrict__ bias, const float* __restrict__ res,
             void* __restrict__ outv, int M, int N, int K) {
    extern __shared__ __half smem_h[];
    __half* As = smem_h;
    __half* Bs = smem_h + NSTAGE * AH_STAGE;

    int tid  = threadIdx.x;
    int lane = tid & 31, warp = tid >> 5;
    int grp  = lane >> 2, tig = lane & 3;
    int sub  = lane >> 3, tr8 = lane & 7;
    int m0 = blockIdx.y * 128, n0 = blockIdx.x * 64;
    int wm = (warp & 3) * 32;
    int wn = (warp >> 2) * 32;
    int ldRow = tid >> 2;
    int ldColh = (tid & 3) << 3;

    uint32_t sA = (uint32_t)__cvta_generic_to_shared(As);
    uint32_t sB = (uint32_t)__cvta_generic_to_shared(Bs);

    int rowAh[2], rowBh[2];
#pragma unroll
    for (int i = 0; i < 2; i++)
        rowAh[i] = (wm + i * 16 + (sub & 1) * 8 + tr8) * 40 + (sub >> 1) * 8;
#pragma unroll
    for (int g = 0; g < 2; g++)
        rowBh[g] = (wn + g * 16 + (sub & 1) * 8 + tr8) * 40 + (sub >> 1) * 8;

    float acc[2][4][4] = {};
    const int niter = K >> 5;

#define ISSUE(it) do {                                                        \
        int s_ = (it) % NSTAGE; int k0_ = (it) << 5;                          \
        _Pragma("unroll")                                                     \
        for (int r = 0; r < 128; r += 64)                                     \
            cp16(sA + 2u*(s_*AH_STAGE + (ldRow + r)*40 + ldColh),             \
                 A + (size_t)(m0 + ldRow + r) * K + k0_ + ldColh);            \
        cp16(sB + 2u*(s_*BH_STAGE + ldRow*40 + ldColh),                       \
             W + (size_t)(n0 + ldRow) * K + k0_ + ldColh);                    \
    } while (0)

#pragma unroll
    for (int p = 0; p < NSTAGE - 1; p++) {
        if (p < niter) { ISSUE(p); }
        asm volatile("cp.async.commit_group;");
    }

    for (int it = 0; it < niter; it++) {
        asm volatile("cp.async.wait_group %0;" :: "n"(NSTAGE - 2));
        __syncthreads();
        if (it + NSTAGE - 1 < niter) { ISSUE(it + NSTAGE - 1); }
        asm volatile("cp.async.commit_group;");

        uint32_t baseA = sA + 2u * ((it % NSTAGE) * AH_STAGE);
        uint32_t baseB = sB + 2u * ((it % NSTAGE) * BH_STAGE);
#pragma unroll
        for (int ks = 0; ks < 2; ks++) {
            int kb = ks * 16;
            uint32_t a[2][4], b[2][4];
#pragma unroll
            for (int i = 0; i < 2; i++)
                ldsm4(a[i], baseA + 2u * (rowAh[i] + kb));
            ldsm4(b[0], baseB + 2u * (rowBh[0] + kb));
            ldsm4(b[1], baseB + 2u * (rowBh[1] + kb));
#pragma unroll
            for (int i = 0; i < 2; i++)
#pragma unroll
                for (int j = 0; j < 4; j++) {
                    int g = j >> 1, jn = j & 1;
                    mma_f16(acc[i][j], a[i][0], a[i][1], a[i][2], a[i][3],
                            b[g][jn], b[g][2 + jn]);
                }
        }
    }
#undef ISSUE

    epilogue<EPI>(acc, m0, n0, wm, wn, grp, tig, bias, res, outv, N);
}

// ---------------- windowed attention (fp16 MMA) ---------------------------
__global__ __launch_bounds__(128)
void attn_kernel(const __half* __restrict__ qkv,
                 const float* __restrict__ biasT,    // [NHEAD][64*64]
                 const float* __restrict__ mask,     // [768][64*64]
                 __half* __restrict__ out) {         // [M,192] half
    __shared__ __half qs[NTOK][40];
    __shared__ __half ks_[NTOK][40];
    __shared__ __half vt[HDIM][72];
    __shared__ float  S[NTOK][NTOK];
    __shared__ __half Ph[NTOK][72];

    int wg = blockIdx.x, head = blockIdx.y, tid = threadIdx.x;
    int lane = tid & 31, warp = tid >> 5;
    int grp = lane >> 2, tig = lane & 3;
    int sub = lane >> 3, tr8 = lane & 7;

    const __half* base = qkv + (size_t)wg * NTOK * C3 + head * HDIM;
    for (int t = tid; t < 256; t += 128) {
        int n = t >> 2, c = t & 3;
        const __half* row = base + (size_t)n * C3 + c * 8;
        *(uint4*)&qs[n][c * 8]  = *(const uint4*)(row);
        *(uint4*)&ks_[n][c * 8] = *(const uint4*)(row + CC);
        uint4 vv = *(const uint4*)(row + 2 * CC);
        __half tmp[8]; *(uint4*)tmp = vv;
#pragma unroll
        for (int i = 0; i < 8; i++) vt[c * 8 + i][n] = tmp[i];
    }
    __syncthreads();

    uint32_t sq = (uint32_t)__cvta_generic_to_shared(qs);
    uint32_t sk = (uint32_t)__cvta_generic_to_shared(ks_);
    uint32_t sv = (uint32_t)__cvta_generic_to_shared(vt);
    uint32_t sp = (uint32_t)__cvta_generic_to_shared(Ph);

    int n0 = warp * 16;
    int rowA8 = n0 + (sub & 1) * 8 + tr8;
    int kA = (sub >> 1) * 8;

    float sc[8][4] = {};
#pragma unroll
    for (int ks = 0; ks < 2; ks++) {
        uint32_t a[4];
        ldsm4(a, sq + 2u * (rowA8 * 40 + kA + ks * 16));
#pragma unroll
        for (int g = 0; g < 4; g++) {
            uint32_t b[4];
            int rowB = g * 16 + (sub & 1) * 8 + tr8;
            ldsm4(b, sk + 2u * (rowB * 40 + kA + ks * 16));
#pragma unroll
            for (int jn = 0; jn < 2; jn++)
                mma_f16(sc[g * 2 + jn], a[0], a[1], a[2], a[3], b[jn], b[2 + jn]);
        }
    }
    const float* bT   = biasT + head * (NTOK * NTOK);
    const float* mrow = mask + (size_t)(wg % NWIN) * (NTOK * NTOK);
#pragma unroll
    for (int j = 0; j < 8; j++) {
#pragma unroll
        for (int h = 0; h < 2; h++) {
            int n = n0 + grp + h * 8;
            int m = j * 8 + 2 * tig;
            int e = n * 64 + m;
            float2 bb = *(const float2*)(bT + e);
            float2 mk = *(const float2*)(mrow + e);
            S[n][m]     = sc[j][h * 2 + 0] * SCALE + bb.x + mk.x;
            S[n][m + 1] = sc[j][h * 2 + 1] * SCALE + bb.y + mk.y;
        }
    }
    __syncthreads();

    for (int r = 0; r < 16; r++) {
        int row = warp * 16 + r;
        float v0 = S[row][lane], v1 = S[row][lane + 32];
        float mx = fmaxf(v0, v1);
#pragma unroll
        for (int o = 16; o; o >>= 1) mx = fmaxf(mx, __shfl_xor_sync(~0u, mx, o));
        float e0 = expf(v0 - mx), e1 = expf(v1 - mx);
        float s = e0 + e1;
#pragma unroll
        for (int o = 16; o; o >>= 1) s += __shfl_xor_sync(~0u, s, o);
        float inv = 1.f / s;
        S[row][lane] = e0 * inv;
        S[row][lane + 32] = e1 * inv;
    }
    __syncthreads();

    for (int t = tid; t < 2048; t += 128) {
        int n = t >> 5, mp = (t & 31) * 2;
        float2 s2 = *(const float2*)&S[n][mp];
        *(__half2*)&Ph[n][mp] = __floats2half2_rn(s2.x, s2.y);
    }
    __syncthreads();

    float oc[4][4] = {};
#pragma unroll
    for (int ks = 0; ks < 4; ks++) {
        uint32_t a[4];
        ldsm4(a, sp + 2u * (rowA8 * 72 + kA + ks * 16));
#pragma unroll
        for (int g = 0; g < 2; g++) {
            uint32_t b[4];
            int rowB = g * 16 + (sub & 1) * 8 + tr8;
            ldsm4(b, sv + 2u * (rowB * 72 + kA + ks * 16));
#pragma unroll
            for (int jn = 0; jn < 2; jn++)
                mma_f16(oc[g * 2 + jn], a[0], a[1], a[2], a[3], b[jn], b[2 + jn]);
        }
    }
    __half* ob = out + (size_t)wg * NTOK * CC + head * HDIM;
#pragma unroll
    for (int j = 0; j < 4; j++) {
#pragma unroll
        for (int h = 0; h < 2; h++) {
            int n = n0 + grp + h * 8;
            int d = j * 8 + 2 * tig;
            *(__half2*)(ob + (size_t)n * CC + d) =
                __floats2half2_rn(oc[j][h * 2], oc[j][h * 2 + 1]);
        }
    }
}

// ---------------- launch ---------------------------------------------------
extern "C" void kernel_launch(void* const* d_in, const int* in_sizes, int n_in,
                              void* d_out, int out_size) {
    const float* x        = (const float*)d_in[0];
    const float* qkv_w    = (const float*)d_in[1];
    const float* qkv_b    = (const float*)d_in[2];
    const float* rpb      = (const float*)d_in[3];
    const float* proj_w   = (const float*)d_in[4];
    const float* proj_b   = (const float*)d_in[5];
    const float* g1       = (const float*)d_in[6];
    const float* b1       = (const float*)d_in[7];
    const float* g2       = (const float*)d_in[8];
    const float* b2       = (const float*)d_in[9];
    const float* fc1_w    = (const float*)d_in[10];
    const float* fc1_b    = (const float*)d_in[11];
    const float* fc2_w    = (const float*)d_in[12];
    const float* fc2_b    = (const float*)d_in[13];
    const int*   rel_idx  = (const int*)  d_in[14];
    const float* amask    = (const float*)d_in[15];
    float* out = (float*)d_out;

    float *bufA, *bufB, *biasT;
    __half* wh;
    cudaGetSymbolAddress((void**)&bufA, g_bufA);
    cudaGetSymbolAddress((void**)&bufB, g_bufB);
    cudaGetSymbolAddress((void**)&biasT, g_biasT);
    cudaGetSymbolAddress((void**)&wh, g_wh);

    __half* win  = (__half*)bufA;
    __half* qkvb = (__half*)bufB;                  // fp16 qkv
    __half* att  = (__half*)bufA;                  // win dead
    float*  x1   = bufB;                           // qkv dead after attn
    __half* h2   = (__half*)(bufB + (size_t)MTOK * CC);
    __half* mlpc = (__half*)bufA;                  // att dead; MTOK/2 x 768 h

    cudaFuncSetAttribute(gemm_os<EPI_QKVH>, cudaFuncAttributeMaxDynamicSharedMemorySize, OS_SMEM);
    cudaFuncSetAttribute(gemm_os<EPI_PROJ>, cudaFuncAttributeMaxDynamicSharedMemorySize, OS_SMEM);
    cudaFuncSetAttribute(gemm_os<EPI_GELU>, cudaFuncAttributeMaxDynamicSharedMemorySize, OS_SMEM);
    cudaFuncSetAttribute(gemm_tc<EPI_RES>,  cudaFuncAttributeMaxDynamicSharedMemorySize, SMEM_DYN);

    const int LN_BLOCKS = MTOK / 8;

    // 0) prep: fp16 weights + bias pre-gather
    prep_kernel<<<(WTOT + 255) / 256, 256>>>(qkv_w, proj_w, fc1_w, fc2_w, wh);
    bias_gather_kernel<<<(NHEAD*NTOK*NTOK + 255)/256, 256>>>(rpb, rel_idx, biasT);

    // 1) LN1 + shift + window partition (gather) -> fp16
    ln_kernel<true><<<LN_BLOCKS, 256>>>(x, g1, b1, win);

    // 2) QKV GEMM (one-shot K=192) -> fp16 qkv
    gemm_os<EPI_QKVH><<<dim3(C3 / 64, MTOK / 128), 256, OS_SMEM>>>(
        win, wh + WOFF_QKV, qkv_b, nullptr, qkvb, MTOK, C3);

    // 3) attention (fp16 MMA) -> fp16 att
    attn_kernel<<<dim3(BB * NWIN, NHEAD), 128>>>(qkvb, biasT, amask, att);

    // 4) proj GEMM (one-shot) + scatter + residual -> x1 f32
    gemm_os<EPI_PROJ><<<dim3(CC / 64, MTOK / 128), 256, OS_SMEM>>>(
        att, wh + WOFF_PROJ, proj_b, x, x1, MTOK, CC);

    // 5) LN2 -> fp16
    ln_kernel<false><<<LN_BLOCKS, 256>>>(x1, g2, b2, h2);

    // 6/7) MLP in 2 row-chunks (mlpc = MTOK/2 x 768 halves = bufA exactly)
    for (int c = 0; c < 2; c++) {
        size_t roff = (size_t)c * MCHUNK;
        gemm_os<EPI_GELU><<<dim3(MLPH / 64, MCHUNK / 128), 256, OS_SMEM>>>(
            h2 + roff * CC, wh + WOFF_FC1, fc1_b, nullptr, mlpc,
            MCHUNK, MLPH);
        gemm_tc<EPI_RES><<<dim3(CC / 64, MCHUNK / 128), 256, SMEM_DYN>>>(
            mlpc, wh + WOFF_FC2, fc2_b, x1 + roff * CC, out + roff * CC,
            MCHUNK, CC, MLPH);
    }

    (void)in_sizes; (void)n_in; (void)out_size;
}

// round 17
// speedup vs baseline: 1.0375x; 1.0375x over previous
#include <cuda_runtime.h>
#include <cuda_fp16.h>
#include <math.h>
#include <stdint.h>

// ---------------- problem constants ----------------
#define BB     8
#define HH     128
#define WW     384
#define CC     192
#define NHEAD  6
#define WSZ    8
#define SSZ    4
#define HDIM   32
#define NWIN   768
#define NTOK   64
#define HWSZ   (HH*WW)             // 49152
#define MTOK   (BB*HWSZ)           // 393216
#define C3     (3*CC)              // 576
#define MLPH   (4*CC)              // 768
#define SCALE  0.1767766952966369f
#define MCHUNK (MTOK/2)            // 196608 rows per MLP chunk (2 chunks)

// ---------------- scratch (aliased; keep <2GB total for host link) --------
__device__ float g_bufA[(size_t)MTOK * CC];    // win/att/mlp(half) reuse
__device__ float g_bufB[(size_t)MTOK * C3];    // qkv(h) -> (x1 | h2)
__device__ float g_biasT[NHEAD * NTOK * NTOK]; // rpb[rel_idx] pre-gathered
__device__ __half g_wh[C3*CC + CC*CC + MLPH*CC + CC*MLPH]; // fp16 weights

#define WOFF_QKV  0
#define WOFF_PROJ (C3*CC)
#define WOFF_FC1  (C3*CC + CC*CC)
#define WOFF_FC2  (C3*CC + CC*CC + MLPH*CC)
#define WTOT      (C3*CC + CC*CC + MLPH*CC + CC*MLPH)   // 442368

__device__ __forceinline__ int win_to_tok(int m) {
    int b  = m / HWSZ;
    int r  = m - b * HWSZ;
    int w  = r >> 6;
    int nt = r & 63;
    int wrow = w / 48;
    int wcol = w - wrow * 48;
    int sh = (wrow << 3) + (nt >> 3);
    int sw = (wcol << 3) + (nt & 7);
    int fh = (sh + SSZ) & (HH - 1);
    int fw = sw + SSZ; if (fw >= WW) fw -= WW;
    return b * HWSZ + fh * WW + fw;
}

// ---------------- merged prep: all weights -> fp16 -----------------------
__global__ void prep_kernel(const float* __restrict__ qkv_w,
                            const float* __restrict__ proj_w,
                            const float* __restrict__ fc1_w,
                            const float* __restrict__ fc2_w,
                            __half* __restrict__ wh) {
    int i = blockIdx.x * blockDim.x + threadIdx.x;
    if (i >= WTOT) return;
    float v;
    if (i < WOFF_PROJ)      v = qkv_w[i];
    else if (i < WOFF_FC1)  v = proj_w[i - WOFF_PROJ];
    else if (i < WOFF_FC2)  v = fc1_w[i - WOFF_FC1];
    else                    v = fc2_w[i - WOFF_FC2];
    wh[i] = __float2half_rn(v);
}
__global__ void bias_gather_kernel(const float* __restrict__ rpb,
                                   const int* __restrict__ rel_idx,
                                   float* __restrict__ biasT) {
    int i = blockIdx.x * blockDim.x + threadIdx.x;
    if (i >= NHEAD * NTOK * NTOK) return;
    int h = i / (NTOK * NTOK), e = i % (NTOK * NTOK);
    biasT[i] = rpb[rel_idx[e] * NHEAD + h];
}

// ---------------- LayerNorm (one warp per token) -> fp16 out --------------
template<bool GATHER>
__global__ void ln_kernel(const float* __restrict__ x,
                          const float* __restrict__ gamma,
                          const float* __restrict__ beta,
                          __half* __restrict__ out) {
    int warp = blockIdx.x * (blockDim.x >> 5) + (threadIdx.x >> 5);
    if (warp >= MTOK) return;
    int lane = threadIdx.x & 31;
    int src = GATHER ? win_to_tok(warp) : warp;
    const float* xr = x + (size_t)src * CC;
    float v[6], s = 0.f, ss = 0.f;
#pragma unroll
    for (int i = 0; i < 6; i++) {
        float t = xr[lane + i * 32];
        v[i] = t; s += t; ss += t * t;
    }
#pragma unroll
    for (int o = 16; o; o >>= 1) {
        s  += __shfl_xor_sync(0xffffffffu, s,  o);
        ss += __shfl_xor_sync(0xffffffffu, ss, o);
    }
    float mean = s * (1.f / CC);
    float var  = ss * (1.f / CC) - mean * mean;
    float rstd = rsqrtf(var + 1e-5f);
    __half* orow = out + (size_t)warp * CC;
#pragma unroll
    for (int i = 0; i < 6; i++) {
        int c = lane + i * 32;
        orow[c] = __float2half_rn((v[i] - mean) * rstd * gamma[c] + beta[c]);
    }
}

// ---------------- shared MMA helpers --------------------------------------
__device__ __forceinline__ void cp16(uint32_t s, const void* g) {
    asm volatile("cp.async.cg.shared.global [%0], [%1], 16;" :: "r"(s), "l"(g));
}
__device__ __forceinline__ void ldsm4(uint32_t* r, uint32_t addr) {
    asm volatile("ldmatrix.sync.aligned.m8n8.x4.shared.b16 {%0,%1,%2,%3}, [%4];"
        : "=r"(r[0]), "=r"(r[1]), "=r"(r[2]), "=r"(r[3]) : "r"(addr));
}
__device__ __forceinline__ void mma_f16(float c[4],
        uint32_t a0, uint32_t a1, uint32_t a2, uint32_t a3,
        uint32_t b0, uint32_t b1) {
    asm volatile(
        "mma.sync.aligned.m16n8k16.row.col.f32.f16.f16.f32 "
        "{%0,%1,%2,%3},{%4,%5,%6,%7},{%8,%9},{%0,%1,%2,%3};"
        : "+f"(c[0]), "+f"(c[1]), "+f"(c[2]), "+f"(c[3])
        : "r"(a0), "r"(a1), "r"(a2), "r"(a3), "r"(b0), "r"(b1));
}

#define EPI_QKVH 0   // out = half(acc + bias)
#define EPI_PROJ 1   // f32: scatter + residual
#define EPI_GELU 2   // half: gelu(acc + bias)
#define EPI_RES  3   // f32: residual

// common fused epilogue, generalized over warp-tile MI x NJ (m16 x n8 units)
template<int EPI, int MI, int NJ>
__device__ __forceinline__ void epilogue(float acc[MI][NJ][4], int m0, int n0,
        int wm, int wn, int grp, int tig,
        const float* bias, const float* res, void* outv, int N) {
#pragma unroll
    for (int i = 0; i < MI; i++) {
#pragma unroll
        for (int h = 0; h < 2; h++) {
            int m = m0 + wm + i * 16 + grp + h * 8;
            int dst = (EPI == EPI_PROJ) ? win_to_tok(m) : m;
#pragma unroll
            for (int j = 0; j < NJ; j++) {
                int n = n0 + wn + j * 8 + 2 * tig;
                float v0 = acc[i][j][h * 2 + 0] + bias[n];
                float v1 = acc[i][j][h * 2 + 1] + bias[n + 1];
                size_t oi = (size_t)dst * N + n;
                if (EPI == EPI_QKVH) {
                    *(__half2*)((__half*)outv + oi) = __floats2half2_rn(v0, v1);
                } else if (EPI == EPI_GELU) {
                    v0 = 0.5f * v0 * (1.f + erff(v0 * 0.70710678118654752f));
                    v1 = 0.5f * v1 * (1.f + erff(v1 * 0.70710678118654752f));
                    *(__half2*)((__half*)outv + oi) = __floats2half2_rn(v0, v1);
                } else {
                    float2 rv = *(const float2*)(res + oi);
                    float2 o = { v0 + rv.x, v1 + rv.y };
                    *(float2*)((float*)outv + oi) = o;
                }
            }
        }
    }
}

// ---------------- one-shot GEMM for K=192, templated BN -------------------
// Whole K-panel in smem (stride 200 halves; conflict-free LDSM octets). ONE
// fill + ONE barrier, then a fully unrolled 12-step MMA loop. A row = 192
// halves = 24 x 16B chunks. BM=128; BN in {64,96,128}:
//   BN=64 : 4Mx2N warps, warp tile 32x32 (MI=2,NJ=4,NB=2)
//   BN=96 : 4Mx2N warps, warp tile 32x48 (MI=2,NJ=6,NB=3)  ratio 2.4
//   BN=128: 2Mx4N warps, warp tile 64x32 (MI=4,NJ=4,NB=2)  ratio 2.67
#define OS_STRIDE 200
#define OS_SMEM(BN)   ((128 + (BN)) * OS_STRIDE * 2)

template<int EPI, int BN>
__global__ __launch_bounds__(256, 2)
void gemm_os(const __half* __restrict__ A, const __half* __restrict__ W,
             const float* __restrict__ bias, const float* __restrict__ res,
             void* __restrict__ outv, int M, int N) {
    constexpr int NWM = (BN == 128) ? 2 : 4;       // warps over M
    constexpr int WTM = 128 / NWM;                 // 64 or 32
    constexpr int WTN = BN / (8 / NWM);            // 32 / 48 / 32
    constexpr int MI  = WTM / 16;
    constexpr int NJ  = WTN / 8;
    constexpr int NB  = WTN / 16;

    extern __shared__ __half smem_h[];
    __half* As = smem_h;                           // 128 * OS_STRIDE
    __half* Bs = smem_h + 128 * OS_STRIDE;         // BN  * OS_STRIDE

    int tid  = threadIdx.x;
    int lane = tid & 31, warp = tid >> 5;
    int grp  = lane >> 2, tig = lane & 3;
    int sub  = lane >> 3, tr8 = lane & 7;
    int m0 = blockIdx.y * 128, n0 = blockIdx.x * BN;
    int wm, wn;
    if (NWM == 4) { wm = (warp & 3) * 32; wn = (warp >> 2) * WTN; }
    else          { wm = (warp & 1) * 64; wn = (warp >> 1) * WTN; }

    uint32_t sA = (uint32_t)__cvta_generic_to_shared(As);
    uint32_t sB = (uint32_t)__cvta_generic_to_shared(Bs);

    // fill: rows have 24 x 16B chunks (192 halves).
#pragma unroll
    for (int i = 0; i < 12; i++) {                 // A: 128*24 = 3072 chunks
        int c = tid + i * 256;
        int r = c / 24, col = (c % 24) * 8;
        cp16(sA + 2u * (r * OS_STRIDE + col),
             A + (size_t)(m0 + r) * CC + col);
    }
#pragma unroll
    for (int i = 0; i < (BN * 24) / 256; i++) {    // B: BN*24 chunks
        int c = tid + i * 256;
        int r = c / 24, col = (c % 24) * 8;
        cp16(sB + 2u * (r * OS_STRIDE + col),
             W + (size_t)(n0 + r) * CC + col);
    }
    asm volatile("cp.async.commit_group;");
    asm volatile("cp.async.wait_group 0;");
    __syncthreads();

    int rowAh[MI], rowBh[NB];
#pragma unroll
    for (int i = 0; i < MI; i++)
        rowAh[i] = (wm + i * 16 + (sub & 1) * 8 + tr8) * OS_STRIDE + (sub >> 1) * 8;
#pragma unroll
    for (int g = 0; g < NB; g++)
        rowBh[g] = (wn + g * 16 + (sub & 1) * 8 + tr8) * OS_STRIDE + (sub >> 1) * 8;

    float acc[MI][NJ][4] = {};
#pragma unroll
    for (int ks = 0; ks < 12; ks++) {
        int kb = ks * 16;
        uint32_t a[MI][4], b[NB][4];
#pragma unroll
        for (int i = 0; i < MI; i++)
            ldsm4(a[i], sA + 2u * (rowAh[i] + kb));
#pragma unroll
        for (int g = 0; g < NB; g++)
            ldsm4(b[g], sB + 2u * (rowBh[g] + kb));
#pragma unroll
        for (int i = 0; i < MI; i++)
#pragma unroll
            for (int j = 0; j < NJ; j++) {
                int g = j >> 1, jn = j & 1;
                mma_f16(acc[i][j], a[i][0], a[i][1], a[i][2], a[i][3],
                        b[g][jn], b[g][2 + jn]);
            }
    }

    epilogue<EPI, MI, NJ>(acc, m0, n0, wm, wn, grp, tig, bias, res, outv, N);
}

// ---------------- pipelined GEMM (used for fc2, K=768) --------------------
#define NSTAGE   4
#define AH_STAGE (128*40)
#define BH_STAGE (64*40)
#define SMEM_DYN (NSTAGE * (AH_STAGE + BH_STAGE) * 2)

template<int EPI>
__global__ __launch_bounds__(256, 3)
void gemm_tc(const __half* __restrict__ A, const __half* __restrict__ W,
             const float* __restrict__ bias, const float* __restrict__ res,
             void* __restrict__ outv, int M, int N, int K) {
    extern __shared__ __half smem_h[];
    __half* As = smem_h;
    __half* Bs = smem_h + NSTAGE * AH_STAGE;

    int tid  = threadIdx.x;
    int lane = tid & 31, warp = tid >> 5;
    int grp  = lane >> 2, tig = lane & 3;
    int sub  = lane >> 3, tr8 = lane & 7;
    int m0 = blockIdx.y * 128, n0 = blockIdx.x * 64;
    int wm = (warp & 3) * 32;
    int wn = (warp >> 2) * 32;
    int ldRow = tid >> 2;
    int ldColh = (tid & 3) << 3;

    uint32_t sA = (uint32_t)__cvta_generic_to_shared(As);
    uint32_t sB = (uint32_t)__cvta_generic_to_shared(Bs);

    int rowAh[2], rowBh[2];
#pragma unroll
    for (int i = 0; i < 2; i++)
        rowAh[i] = (wm + i * 16 + (sub & 1) * 8 + tr8) * 40 + (sub >> 1) * 8;
#pragma unroll
    for (int g = 0; g < 2; g++)
        rowBh[g] = (wn + g * 16 + (sub & 1) * 8 + tr8) * 40 + (sub >> 1) * 8;

    float acc[2][4][4] = {};
    const int niter = K >> 5;

#define ISSUE(it) do {                                                        \
        int s_ = (it) % NSTAGE; int k0_ = (it) << 5;                          \
        _Pragma("unroll")                                                     \
        for (int r = 0; r < 128; r += 64)                                     \
            cp16(sA + 2u*(s_*AH_STAGE + (ldRow + r)*40 + ldColh),             \
                 A + (size_t)(m0 + ldRow + r) * K + k0_ + ldColh);            \
        cp16(sB + 2u*(s_*BH_STAGE + ldRow*40 + ldColh),                       \
             W + (size_t)(n0 + ldRow) * K + k0_ + ldColh);                    \
    } while (0)

#pragma unroll
    for (int p = 0; p < NSTAGE - 1; p++) {
        if (p < niter) { ISSUE(p); }
        asm volatile("cp.async.commit_group;");
    }

    for (int it = 0; it < niter; it++) {
        asm volatile("cp.async.wait_group %0;" :: "n"(NSTAGE - 2));
        __syncthreads();
        if (it + NSTAGE - 1 < niter) { ISSUE(it + NSTAGE - 1); }
        asm volatile("cp.async.commit_group;");

        uint32_t baseA = sA + 2u * ((it % NSTAGE) * AH_STAGE);
        uint32_t baseB = sB + 2u * ((it % NSTAGE) * BH_STAGE);
#pragma unroll
        for (int ks = 0; ks < 2; ks++) {
            int kb = ks * 16;
            uint32_t a[2][4], b[2][4];
#pragma unroll
            for (int i = 0; i < 2; i++)
                ldsm4(a[i], baseA + 2u * (rowAh[i] + kb));
            ldsm4(b[0], baseB + 2u * (rowBh[0] + kb));
            ldsm4(b[1], baseB + 2u * (rowBh[1] + kb));
#pragma unroll
            for (int i = 0; i < 2; i++)
#pragma unroll
                for (int j = 0; j < 4; j++) {
                    int g = j >> 1, jn = j & 1;
                    mma_f16(acc[i][j], a[i][0], a[i][1], a[i][2], a[i][3],
                            b[g][jn], b[g][2 + jn]);
                }
        }
    }
#undef ISSUE

    epilogue<EPI, 2, 4>(acc, m0, n0, wm, wn, grp, tig, bias, res, outv, N);
}

// ---------------- windowed attention (fp16 MMA) ---------------------------
__global__ __launch_bounds__(128)
void attn_kernel(const __half* __restrict__ qkv,
                 const float* __restrict__ biasT,    // [NHEAD][64*64]
                 const float* __restrict__ mask,     // [768][64*64]
                 __half* __restrict__ out) {         // [M,192] half
    __shared__ __half qs[NTOK][40];
    __shared__ __half ks_[NTOK][40];
    __shared__ __half vt[HDIM][72];
    __shared__ float  S[NTOK][NTOK];
    __shared__ __half Ph[NTOK][72];

    int wg = blockIdx.x, head = blockIdx.y, tid = threadIdx.x;
    int lane = tid & 31, warp = tid >> 5;
    int grp = lane >> 2, tig = lane & 3;
    int sub = lane >> 3, tr8 = lane & 7;

    const __half* base = qkv + (size_t)wg * NTOK * C3 + head * HDIM;
    for (int t = tid; t < 256; t += 128) {
        int n = t >> 2, c = t & 3;
        const __half* row = base + (size_t)n * C3 + c * 8;
        *(uint4*)&qs[n][c * 8]  = *(const uint4*)(row);
        *(uint4*)&ks_[n][c * 8] = *(const uint4*)(row + CC);
        uint4 vv = *(const uint4*)(row + 2 * CC);
        __half tmp[8]; *(uint4*)tmp = vv;
#pragma unroll
        for (int i = 0; i < 8; i++) vt[c * 8 + i][n] = tmp[i];
    }
    __syncthreads();

    uint32_t sq = (uint32_t)__cvta_generic_to_shared(qs);
    uint32_t sk = (uint32_t)__cvta_generic_to_shared(ks_);
    uint32_t sv = (uint32_t)__cvta_generic_to_shared(vt);
    uint32_t sp = (uint32_t)__cvta_generic_to_shared(Ph);

    int n0 = warp * 16;
    int rowA8 = n0 + (sub & 1) * 8 + tr8;
    int kA = (sub >> 1) * 8;

    float sc[8][4] = {};
#pragma unroll
    for (int ks = 0; ks < 2; ks++) {
        uint32_t a[4];
        ldsm4(a, sq + 2u * (rowA8 * 40 + kA + ks * 16));
#pragma unroll
        for (int g = 0; g < 4; g++) {
            uint32_t b[4];
            int rowB = g * 16 + (sub & 1) * 8 + tr8;
            ldsm4(b, sk + 2u * (rowB * 40 + kA + ks * 16));
#pragma unroll
            for (int jn = 0; jn < 2; jn++)
                mma_f16(sc[g * 2 + jn], a[0], a[1], a[2], a[3], b[jn], b[2 + jn]);
        }
    }
    const float* bT   = biasT + head * (NTOK * NTOK);
    const float* mrow = mask + (size_t)(wg % NWIN) * (NTOK * NTOK);
#pragma unroll
    for (int j = 0; j < 8; j++) {
#pragma unroll
        for (int h = 0; h < 2; h++) {
            int n = n0 + grp + h * 8;
            int m = j * 8 + 2 * tig;
            int e = n * 64 + m;
            float2 bb = *(const float2*)(bT + e);
            float2 mk = *(const float2*)(mrow + e);
            S[n][m]     = sc[j][h * 2 + 0] * SCALE + bb.x + mk.x;
            S[n][m + 1] = sc[j][h * 2 + 1] * SCALE + bb.y + mk.y;
        }
    }
    __syncthreads();

    for (int r = 0; r < 16; r++) {
        int row = warp * 16 + r;
        float v0 = S[row][lane], v1 = S[row][lane + 32];
        float mx = fmaxf(v0, v1);
#pragma unroll
        for (int o = 16; o; o >>= 1) mx = fmaxf(mx, __shfl_xor_sync(~0u, mx, o));
        float e0 = expf(v0 - mx), e1 = expf(v1 - mx);
        float s = e0 + e1;
#pragma unroll
        for (int o = 16; o; o >>= 1) s += __shfl_xor_sync(~0u, s, o);
        float inv = 1.f / s;
        S[row][lane] = e0 * inv;
        S[row][lane + 32] = e1 * inv;
    }
    __syncthreads();

    for (int t = tid; t < 2048; t += 128) {
        int n = t >> 5, mp = (t & 31) * 2;
        float2 s2 = *(const float2*)&S[n][mp];
        *(__half2*)&Ph[n][mp] = __floats2half2_rn(s2.x, s2.y);
    }
    __syncthreads();

    float oc[4][4] = {};
#pragma unroll
    for (int ks = 0; ks < 4; ks++) {
        uint32_t a[4];
        ldsm4(a, sp + 2u * (rowA8 * 72 + kA + ks * 16));
#pragma unroll
        for (int g = 0; g < 2; g++) {
            uint32_t b[4];
            int rowB = g * 16 + (sub & 1) * 8 + tr8;
            ldsm4(b, sv + 2u * (rowB * 72 + kA + ks * 16));
#pragma unroll
            for (int jn = 0; jn < 2; jn++)
                mma_f16(oc[g * 2 + jn], a[0], a[1], a[2], a[3], b[jn], b[2 + jn]);
        }
    }
    __half* ob = out + (size_t)wg * NTOK * CC + head * HDIM;
#pragma unroll
    for (int j = 0; j < 4; j++) {
#pragma unroll
        for (int h = 0; h < 2; h++) {
            int n = n0 + grp + h * 8;
            int d = j * 8 + 2 * tig;
            *(__half2*)(ob + (size_t)n * CC + d) =
                __floats2half2_rn(oc[j][h * 2], oc[j][h * 2 + 1]);
        }
    }
}

// ---------------- launch ---------------------------------------------------
extern "C" void kernel_launch(void* const* d_in, const int* in_sizes, int n_in,
                              void* d_out, int out_size) {
    const float* x        = (const float*)d_in[0];
    const float* qkv_w    = (const float*)d_in[1];
    const float* qkv_b    = (const float*)d_in[2];
    const float* rpb      = (const float*)d_in[3];
    const float* proj_w   = (const float*)d_in[4];
    const float* proj_b   = (const float*)d_in[5];
    const float* g1       = (const float*)d_in[6];
    const float* b1       = (const float*)d_in[7];
    const float* g2       = (const float*)d_in[8];
    const float* b2       = (const float*)d_in[9];
    const float* fc1_w    = (const float*)d_in[10];
    const float* fc1_b    = (const float*)d_in[11];
    const float* fc2_w    = (const float*)d_in[12];
    const float* fc2_b    = (const float*)d_in[13];
    const int*   rel_idx  = (const int*)  d_in[14];
    const float* amask    = (const float*)d_in[15];
    float* out = (float*)d_out;

    float *bufA, *bufB, *biasT;
    __half* wh;
    cudaGetSymbolAddress((void**)&bufA, g_bufA);
    cudaGetSymbolAddress((void**)&bufB, g_bufB);
    cudaGetSymbolAddress((void**)&biasT, g_biasT);
    cudaGetSymbolAddress((void**)&wh, g_wh);

    __half* win  = (__half*)bufA;
    __half* qkvb = (__half*)bufB;                  // fp16 qkv
    __half* att  = (__half*)bufA;                  // win dead
    float*  x1   = bufB;                           // qkv dead after attn
    __half* h2   = (__half*)(bufB + (size_t)MTOK * CC);
    __half* mlpc = (__half*)bufA;                  // att dead; MTOK/2 x 768 h

    cudaFuncSetAttribute(gemm_os<EPI_QKVH, 96>,  cudaFuncAttributeMaxDynamicSharedMemorySize, OS_SMEM(96));
    cudaFuncSetAttribute(gemm_os<EPI_PROJ, 96>,  cudaFuncAttributeMaxDynamicSharedMemorySize, OS_SMEM(96));
    cudaFuncSetAttribute(gemm_os<EPI_GELU, 128>, cudaFuncAttributeMaxDynamicSharedMemorySize, OS_SMEM(128));
    cudaFuncSetAttribute(gemm_tc<EPI_RES>,       cudaFuncAttributeMaxDynamicSharedMemorySize, SMEM_DYN);

    const int LN_BLOCKS = MTOK / 8;

    // 0) prep: fp16 weights + bias pre-gather
    prep_kernel<<<(WTOT + 255) / 256, 256>>>(qkv_w, proj_w, fc1_w, fc2_w, wh);
    bias_gather_kernel<<<(NHEAD*NTOK*NTOK + 255)/256, 256>>>(rpb, rel_idx, biasT);

    // 1) LN1 + shift + window partition (gather) -> fp16
    ln_kernel<true><<<LN_BLOCKS, 256>>>(x, g1, b1, win);

    // 2) QKV GEMM (one-shot, BN=96) -> fp16 qkv   (576 = 6*96)
    gemm_os<EPI_QKVH, 96><<<dim3(C3 / 96, MTOK / 128), 256, OS_SMEM(96)>>>(
        win, wh + WOFF_QKV, qkv_b, nullptr, qkvb, MTOK, C3);

    // 3) attention (fp16 MMA) -> fp16 att
    attn_kernel<<<dim3(BB * NWIN, NHEAD), 128>>>(qkvb, biasT, amask, att);

    // 4) proj GEMM (one-shot, BN=96) + scatter + residual -> x1 f32 (192=2*96)
    gemm_os<EPI_PROJ, 96><<<dim3(CC / 96, MTOK / 128), 256, OS_SMEM(96)>>>(
        att, wh + WOFF_PROJ, proj_b, x, x1, MTOK, CC);

    // 5) LN2 -> fp16
    ln_kernel<false><<<LN_BLOCKS, 256>>>(x1, g2, b2, h2);

    // 6/7) MLP in 2 row-chunks (mlpc = MTOK/2 x 768 halves = bufA exactly)
    for (int c = 0; c < 2; c++) {
        size_t roff = (size_t)c * MCHUNK;
        // fc1: one-shot BN=128 (768 = 6*128)
        gemm_os<EPI_GELU, 128><<<dim3(MLPH / 128, MCHUNK / 128), 256, OS_SMEM(128)>>>(
            h2 + roff * CC, wh + WOFF_FC1, fc1_b, nullptr, mlpc,
            MCHUNK, MLPH);
        // fc2: pipelined K=768
        gemm_tc<EPI_RES><<<dim3(CC / 64, MCHUNK / 128), 256, SMEM_DYN>>>(
            mlpc, wh + WOFF_FC2, fc2_b, x1 + roff * CC, out + roff * CC,
            MCHUNK, CC, MLPH);
    }

    (void)in_sizes; (void)n_in; (void)out_size;
}